// round 14
// baseline (speedup 1.0000x reference)
#include <cuda_runtime.h>

#define Bb 8
#define Cc 128
#define Hh 128
#define Ww 128
#define HW 16384
#define NELEM (Bb*Cc*HW)
#define DD 2048
#define BH 64

// ---------------- scratch ----------------------------------------------------
__device__ float g_x1[NELEM];     // LN out; later out1
__device__ float g_y[NELEM];      // y1; later out4
__device__ float g_s[NELEM];      // x_tf32; then bn-relu sum; later out3
__device__ float g_out2[NELEM];   // out2; later merged o3+o4
__device__ float g_hwc1[NELEM];   // y2; then hwc(out1)
__device__ float g_whc1[NELEM];   // y3; then whc(out1)
__device__ float g_whc2[NELEM];   // att; then whc(out2)
__device__ float g_A1[BH*Hh*Ww];
__device__ float g_A2[BH*Hh*Ww];
__device__ float g_n_hwc1[BH*Hh];   // raw sumsq
__device__ float g_n_whc1[BH*Ww];   // raw sumsq (atomic-accumulated)
__device__ float g_n_whc2[BH*Ww];   // raw sumsq (atomic-accumulated)
__device__ float g_acc[3*256];      // per-conv sum/sumsq accumulators
__device__ float g_wp1[Cc*Cc];
__device__ float g_wp2[9*Cc*Cc];
__device__ float g_wp3[9*Cc*Cc];
__device__ float g_wpo1[Cc*Cc];
__device__ float g_wpo2[Cc*Cc];

// ---------------- tf32 helpers ----------------------------------------------
__device__ __forceinline__ unsigned cvt1(float f) {
    unsigned u; asm("cvt.rna.tf32.f32 %0, %1;" : "=r"(u) : "f"(f)); return u;
}
__device__ __forceinline__ void mma_tf32(float* c, unsigned a0, unsigned a1,
                                         unsigned a2, unsigned a3,
                                         unsigned b0, unsigned b1) {
    asm volatile("mma.sync.aligned.m16n8k8.row.col.f32.tf32.tf32.f32 "
                 "{%0,%1,%2,%3}, {%4,%5,%6,%7}, {%8,%9}, {%0,%1,%2,%3};"
                 : "+f"(c[0]), "+f"(c[1]), "+f"(c[2]), "+f"(c[3])
                 : "r"(a0), "r"(a1), "r"(a2), "r"(a3), "r"(b0), "r"(b1));
}
__device__ __forceinline__ void cpa8(unsigned dst, const void* src, int sz) {
    asm volatile("cp.async.ca.shared.global [%0], [%1], 8, %2;" :: "r"(dst), "l"(src), "r"(sz));
}
__device__ __forceinline__ void cpa16(unsigned dst, const void* src) {
    asm volatile("cp.async.cg.shared.global [%0], [%1], 16;" :: "r"(dst), "l"(src));
}
__device__ __forceinline__ void cpa_commit() { asm volatile("cp.async.commit_group;"); }
__device__ __forceinline__ void cpa_wait0() { asm volatile("cp.async.wait_group 0;"); }
__device__ __forceinline__ void cpa_wait1() { asm volatile("cp.async.wait_group 1;"); }

// ---------------- single-launch weight pack + accumulator zeroing ------------
__device__ __forceinline__ void pack_one(const float* __restrict__ w,
                                         float* __restrict__ wp, int taps, int idx) {
    int co = idx / (Cc * taps);
    int rem = idx % (Cc * taps);
    int ci = rem / taps;
    int tap = rem % taps;
    wp[(tap * Cc + ci) * Cc + co] = __uint_as_float(cvt1(w[idx]));
}
__global__ void pack_all(const float* __restrict__ wd1, const float* __restrict__ wd2,
                         const float* __restrict__ wd3, const float* __restrict__ wo1,
                         const float* __restrict__ wo2) {
    int idx = blockIdx.x * 256 + threadIdx.x;
    if (idx < 768) g_acc[idx] = 0.f;
    if (idx < BH * Ww) g_n_whc1[idx] = 0.f;
    else if (idx < 2 * BH * Ww) g_n_whc2[idx - BH * Ww] = 0.f;
    if (idx < 16384)            pack_one(wd1, g_wp1, 1, idx);
    else if (idx < 163840)      pack_one(wd2, g_wp2, 9, idx - 16384);
    else if (idx < 311296)      pack_one(wd3, g_wp3, 9, idx - 163840);
    else if (idx < 327680)      pack_one(wo1, g_wpo1, 1, idx - 311296);
    else if (idx < 344064)      pack_one(wo2, g_wpo2, 1, idx - 327680);
}

// ---------------- LN + rounded-x, single global read -------------------------
__global__ __launch_bounds__(128) void ln_round(const float* __restrict__ x,
                                                const float* __restrict__ lw,
                                                const float* __restrict__ lb,
                                                float* __restrict__ o,
                                                float* __restrict__ xr) {
    extern __shared__ float row[];
    int bi = blockIdx.x;
    int b = bi >> 7, i = bi & 127;
    int w = threadIdx.x;
    size_t off = (size_t)b * Cc * HW + i * Ww + w;
    const float* p = x + off;
    float s = 0.f, sq = 0.f;
    for (int c = 0; c < Cc; c++) {
        float v = p[(size_t)c * HW];
        row[c * 128 + w] = v;
        s += v; sq += v * v;
    }
    float mu = s * (1.f / Cc);
    float var = sq * (1.f / Cc) - mu * mu;
    float r = rsqrtf(var + 1e-5f);
    float* op = o + off;
    float* xp = xr + off;
    for (int c = 0; c < Cc; c++) {
        float v = row[c * 128 + w];
        op[(size_t)c * HW] = (v - mu) * r * lw[c] + lb[c];
        xp[(size_t)c * HW] = __uint_as_float(cvt1(v));
    }
}

// ---------------- conv GEMM: 128 threads, 64x64 warp tiles, 3-stage ----------
struct ConvJob {
    const float* in;
    const float* wp;
    const float* resid;
    float* out;
    float* acc;
    int taps, dil, rnd;
};

__global__ __launch_bounds__(128, 2) void conv_gemm(ConvJob j0, ConvJob j1, ConvJob j2) {
    extern __shared__ unsigned smem[];
    unsigned (*Asm)[136] = (unsigned(*)[136])smem;
    unsigned (*Bsm)[136] = (unsigned(*)[136])(smem + 3 * 32 * 136);
    ConvJob j = (blockIdx.y == 0) ? j0 : (blockIdx.y == 1 ? j1 : j2);
    const int taps = j.taps, dil = j.dil;
    int bi = blockIdx.x;
    int b = bi >> 7, i = bi & 127;
    int tid = threadIdx.x, lane = tid & 31, wid = tid >> 5;
    int gid = lane >> 2, tig = lane & 3;
    int m_base = (wid >> 1) * 64, n_base = (wid & 1) * 64;
    float C[4][8][4];
#pragma unroll
    for (int a = 0; a < 4; a++)
#pragma unroll
        for (int c = 0; c < 8; c++)
#pragma unroll
            for (int d = 0; d < 4; d++) C[a][c][d] = 0.f;
    const int nch = taps * 4;
    const float* inb = j.in + (size_t)b * Cc * HW;
    const int w2 = (tid & 63) * 2;      // taps==9 B: pair column
    const int kb2 = tid >> 6;           // taps==9 B: k parity (0..1), step 2
    const int w4 = (tid & 31) * 4;      // taps==1 B: 4-wide column
    const int kb4 = tid >> 5;           // taps==1 B: k base (0..3), step 4

    auto issueA = [&](int ch, int st) {
        const float* wpB = j.wp + (size_t)ch * 32 * 128;
        unsigned base = (unsigned)__cvta_generic_to_shared(&Asm[st * 32][0]);
#pragma unroll
        for (int r = 0; r < 8; r++) {
            int u = tid + r * 128;
            int kka = u >> 5, m4 = (u & 31) * 4;
            cpa16(base + (unsigned)((kka * 136 + m4) * 4), wpB + kka * 128 + m4);
        }
    };
    auto issueB = [&](int ch, int st) {
        unsigned dst0 = (unsigned)__cvta_generic_to_shared(&Bsm[st * 32][0]);
        if (taps == 9) {
            int tap = ch >> 2, ciBase = (ch & 3) * 32;
            int dy = (tap / 3 - 1) * dil, dx = (tap % 3 - 1) * dil;
            int ii = i + dy;
            int wd = w2 + dx;
            int ok = ((unsigned)ii < 128u && (unsigned)wd < 127u) ? 8 : 0;
            const float* src = inb + (size_t)(ciBase + kb2) * HW + ii * 128 + wd;
            unsigned dst = dst0 + (unsigned)((kb2 * 136 + w2) * 4);
#pragma unroll
            for (int r = 0; r < 16; r++)
                cpa8(dst + (unsigned)(r * 2 * 136 * 4), src + (size_t)r * 2 * HW, ok);
        } else {
            int ciBase = ch * 32;
            const float* src = inb + (size_t)(ciBase + kb4) * HW + i * 128 + w4;
            unsigned dst = dst0 + (unsigned)((kb4 * 136 + w4) * 4);
#pragma unroll
            for (int r = 0; r < 8; r++)
                cpa16(dst + (unsigned)(r * 4 * 136 * 4), src + (size_t)r * 4 * HW);
        }
    };

    issueA(0, 0); issueB(0, 0); cpa_commit();
    issueA(1, 1); issueB(1, 1); cpa_commit();

    for (int ch = 0; ch < nch; ch++) {
        if (ch + 2 < nch) cpa_wait1(); else cpa_wait0();
        __syncthreads();
        int st = ch % 3;
        unsigned (*As)[136] = &Asm[st * 32];
        unsigned (*Bs)[136] = &Bsm[st * 32];
#pragma unroll
        for (int ks = 0; ks < 4; ks++) {
            unsigned b0[8], b1[8];
#pragma unroll
            for (int nt = 0; nt < 8; nt++) {
                b0[nt] = Bs[ks * 8 + tig][n_base + nt * 8 + gid];
                b1[nt] = Bs[ks * 8 + tig + 4][n_base + nt * 8 + gid];
            }
#pragma unroll
            for (int mt = 0; mt < 4; mt++) {
                int m = m_base + mt * 16;
                unsigned a0 = As[ks * 8 + tig][m + gid];
                unsigned a1 = As[ks * 8 + tig][m + 8 + gid];
                unsigned a2 = As[ks * 8 + tig + 4][m + gid];
                unsigned a3 = As[ks * 8 + tig + 4][m + 8 + gid];
#pragma unroll
                for (int nt = 0; nt < 8; nt++) mma_tf32(C[mt][nt], a0, a1, a2, a3, b0[nt], b1[nt]);
            }
            if (ks == 0 && ch + 2 < nch) {
                int st2 = (ch + 2) % 3;
                issueA(ch + 2, st2); issueB(ch + 2, st2); cpa_commit();
            }
        }
    }
    float* sacc = (float*)smem;
    if (j.acc) {
        __syncthreads();
        sacc[tid] = 0.f; sacc[128 + tid] = 0.f;
        __syncthreads();
    }
#pragma unroll
    for (int mt = 0; mt < 4; mt++)
#pragma unroll
        for (int half = 0; half < 2; half++) {
            int m = m_base + mt * 16 + gid + half * 8;
            size_t base = ((size_t)(b * 128 + m) * 128 + i) * 128;
            float rs = 0.f, rq = 0.f;
#pragma unroll
            for (int nt = 0; nt < 8; nt++) {
                int n = n_base + nt * 8 + 2 * tig;
                float v0 = C[mt][nt][half * 2 + 0];
                float v1 = C[mt][nt][half * 2 + 1];
                if (j.resid) { v0 += j.resid[base + n]; v1 += j.resid[base + n + 1]; }
                if (j.rnd) { v0 = __uint_as_float(cvt1(v0)); v1 = __uint_as_float(cvt1(v1)); }
                rs += v0 + v1;
                rq += v0 * v0 + v1 * v1;
                float2 t = {v0, v1};
                *(float2*)&j.out[base + n] = t;
            }
            if (j.acc) {
                rs += __shfl_xor_sync(0xffffffffu, rs, 1);
                rs += __shfl_xor_sync(0xffffffffu, rs, 2);
                rq += __shfl_xor_sync(0xffffffffu, rq, 1);
                rq += __shfl_xor_sync(0xffffffffu, rq, 2);
                if (tig == 0) { atomicAdd(&sacc[m], rs); atomicAdd(&sacc[128 + m], rq); }
            }
        }
    if (j.acc) {
        __syncthreads();
        atomicAdd(&j.acc[tid], sacc[tid]);
        atomicAdd(&j.acc[128 + tid], sacc[128 + tid]);
    }
}

// ---------------- BN-ReLU-sum with inline stats finalize ---------------------
__global__ __launch_bounds__(256) void bnrelu3(const float* __restrict__ y1,
                                               const float* __restrict__ y2,
                                               const float* __restrict__ y3,
                                               const float* __restrict__ g1, const float* __restrict__ b1,
                                               const float* __restrict__ g2, const float* __restrict__ b2,
                                               const float* __restrict__ g3, const float* __restrict__ b3,
                                               float* __restrict__ s) {
    int idx = blockIdx.x * 256 + threadIdx.x;
    int c = (idx >> 14) & 127;
    const float inv = 1.f / (float)(Bb * HW);
    float m1 = g_acc[c] * inv;
    float r1 = rsqrtf(g_acc[128 + c] * inv - m1 * m1 + 1e-5f);
    float m2 = g_acc[256 + c] * inv;
    float r2 = rsqrtf(g_acc[384 + c] * inv - m2 * m2 + 1e-5f);
    float m3 = g_acc[512 + c] * inv;
    float r3 = rsqrtf(g_acc[640 + c] * inv - m3 * m3 + 1e-5f);
    float v1 = fmaxf((y1[idx] - m1) * r1 * g1[c] + b1[c], 0.f);
    float v2 = fmaxf((y2[idx] - m2) * r2 * g2[c] + b2[c], 0.f);
    float v3 = fmaxf((y3[idx] - m3) * r3 * g3[c] + b3[c], 0.f);
    s[idx] = __uint_as_float(cvt1(v1 + v2 + v3));
}

// ---------------- six depthwise convs, padded plane --------------------------
#define PS 136
#define PROWS 134
__global__ __launch_bounds__(256) void dw_kernel(const float* __restrict__ x1,
    const float* __restrict__ w1, const float* __restrict__ b1,
    const float* __restrict__ w2, const float* __restrict__ b2,
    const float* __restrict__ w3, const float* __restrict__ b3,
    const float* __restrict__ w4, const float* __restrict__ b4,
    const float* __restrict__ w5, const float* __restrict__ b5,
    const float* __restrict__ w6, const float* __restrict__ b6,
    float* __restrict__ out) {
    extern __shared__ float plane[];
    int bc = blockIdx.x;
    int c = bc & 127;
    const float* p = x1 + (size_t)bc * HW;
    for (int idx = threadIdx.x; idx < PROWS * PS; idx += 256) plane[idx] = 0.f;
    __syncthreads();
    for (int idx = threadIdx.x; idx < HW; idx += 256) {
        int i = idx >> 7, w = idx & 127;
        plane[(i + 3) * PS + (w + 3)] = p[idx];
    }
    float f1[5], f2[5], f4[9], f5[7], f6[7];
#pragma unroll
    for (int j = 0; j < 5; j++) { f1[j] = w1[c * 5 + j]; f2[j] = w2[c * 5 + j]; }
#pragma unroll
    for (int j = 0; j < 9; j++) f4[j] = w4[c * 9 + j];
#pragma unroll
    for (int j = 0; j < 7; j++) { f5[j] = w5[c * 7 + j]; f6[j] = w6[c * 7 + j]; }
    float f3 = w3[c];
    float bias = b1[c] + b2[c] + b3[c] + b4[c] + b5[c] + b6[c];
    __syncthreads();
    for (int idx = threadIdx.x; idx < HW; idx += 256) {
        int i = idx >> 7, w = idx & 127;
        const float* cp = &plane[(i + 3) * PS + (w + 3)];
        float acc = bias + f3 * cp[0];
#pragma unroll
        for (int j = 0; j < 5; j++) acc += f1[j] * cp[j - 2];
#pragma unroll
        for (int j = 0; j < 5; j++) acc += f2[j] * cp[(j - 2) * PS];
#pragma unroll
        for (int pq = 0; pq < 9; pq++) acc += f4[pq] * cp[(pq / 3 - 1) * PS + (pq % 3 - 1)];
#pragma unroll
        for (int j = 0; j < 7; j++) acc += f5[j] * cp[j - 3];
#pragma unroll
        for (int j = 0; j < 7; j++) acc += f6[j] * cp[(j - 3) * PS];
        out[(size_t)bc * HW + idx] = __uint_as_float(cvt1(acc));
    }
}

// ---------------- rearranges + fused row-norm partials -----------------------
__global__ __launch_bounds__(256) void rearrange_both(const float* __restrict__ out1,
                                                      float* __restrict__ hwc,
                                                      float* __restrict__ whc,
                                                      float* __restrict__ nrm,
                                                      float* __restrict__ nacc1,
                                                      const float* __restrict__ out2,
                                                      float* __restrict__ whc2,
                                                      float* __restrict__ nacc2) {
    int r = blockIdx.x;
    int i = r & 127, bh = r >> 7;
    int b = bh >> 3, hd = bh & 7;
    __shared__ float tile[16][129];
    __shared__ float sw[128];
    if (blockIdx.y == 0) {
        __shared__ float red[256];
        float sq = 0.f;
        for (int idx = threadIdx.x; idx < 2048; idx += 256) {
            int c = idx >> 7, w = idx & 127;
            float v = out1[((size_t)(b * Cc + hd * 16 + c) * Hh + i) * Ww + w];
            tile[c][w] = v;
            sq += v * v;
        }
        red[threadIdx.x] = sq;
        __syncthreads();
        for (int o = 128; o; o >>= 1) { if (threadIdx.x < o) red[threadIdx.x] += red[threadIdx.x + o]; __syncthreads(); }
        if (threadIdx.x == 0) nrm[bh * 128 + i] = red[0];
        float* dh = hwc + ((size_t)bh * Hh + i) * DD;
        float* dw = whc + (size_t)bh * Ww * DD + i * 16;
        for (int idx = threadIdx.x; idx < 2048; idx += 256) {
            int w = idx >> 4, c = idx & 15;
            float v = tile[c][w];
            dh[idx] = v;
            dw[(size_t)w * DD + c] = v;
            float s = v * v;
            s += __shfl_xor_sync(0xffffffffu, s, 1);
            s += __shfl_xor_sync(0xffffffffu, s, 2);
            s += __shfl_xor_sync(0xffffffffu, s, 4);
            s += __shfl_xor_sync(0xffffffffu, s, 8);
            if ((threadIdx.x & 15) == 0) sw[w] = s;
        }
        __syncthreads();
        if (threadIdx.x < 128) atomicAdd(&nacc1[bh * 128 + threadIdx.x], sw[threadIdx.x]);
    } else {
        for (int idx = threadIdx.x; idx < 2048; idx += 256) {
            int c = idx >> 7, w = idx & 127;
            tile[c][w] = out2[((size_t)(b * Cc + hd * 16 + c) * Hh + i) * Ww + w];
        }
        __syncthreads();
        float* d = whc2 + (size_t)bh * Ww * DD + i * 16;
        for (int idx = threadIdx.x; idx < 2048; idx += 256) {
            int w = idx >> 4, c = idx & 15;
            float v = tile[c][w];
            d[(size_t)w * DD + c] = v;
            float s = v * v;
            s += __shfl_xor_sync(0xffffffffu, s, 1);
            s += __shfl_xor_sync(0xffffffffu, s, 2);
            s += __shfl_xor_sync(0xffffffffu, s, 4);
            s += __shfl_xor_sync(0xffffffffu, s, 8);
            if ((threadIdx.x & 15) == 0) sw[w] = s;
        }
        __syncthreads();
        if (threadIdx.x < 128) atomicAdd(&nacc2[bh * 128 + threadIdx.x], sw[threadIdx.x]);
    }
}

// ---------------- QK^T + softmax: 3-stage cp.async, raw-sumsq norms ----------
#define QK_STQ (64 * 36)
#define QK_STK (128 * 36)
#define SMEM_QK (3 * (QK_STQ + QK_STK) * 4)

__global__ __launch_bounds__(256) void qk_tf32(const float* __restrict__ Q1,
                                               const float* __restrict__ K1,
                                               const float* __restrict__ qn1,
                                               const float* __restrict__ kn1,
                                               float* __restrict__ A1,
                                               const float* __restrict__ Q2,
                                               const float* __restrict__ K2,
                                               const float* __restrict__ qn2,
                                               const float* __restrict__ kn2,
                                               float* __restrict__ A2) {
    extern __shared__ unsigned qsm[];
    const float* Q; const float* K; const float* qn; const float* kn; float* A;
    if (blockIdx.z == 0) { Q = Q1; K = K1; qn = qn1; kn = kn1; A = A1; }
    else                 { Q = Q2; K = K2; qn = qn2; kn = kn2; A = A2; }
    int bh = blockIdx.x;
    int m0 = blockIdx.y * 64;
    const float* q = Q + (size_t)(bh * 128 + m0) * DD;
    const float* k = K + (size_t)bh * 128 * DD;
    int tid = threadIdx.x, lane = tid & 31, wid = tid >> 5;
    int gid = lane >> 2, tig = lane & 3;
    int m_base = (wid >> 2) * 32, n_base = (wid & 3) * 32;
    float C[2][4][4];
#pragma unroll
    for (int a = 0; a < 2; a++)
#pragma unroll
        for (int c = 0; c < 4; c++)
#pragma unroll
            for (int d = 0; d < 4; d++) C[a][c][d] = 0.f;

    auto issue = [&](int ch, int st) {
        unsigned qb = (unsigned)__cvta_generic_to_shared(qsm + st * QK_STQ);
#pragma unroll
        for (int r = 0; r < 2; r++) {
            int u = tid + r * 256;
            int m = u >> 3, k4 = (u & 7) * 4;
            cpa16(qb + (unsigned)((m * 36 + k4) * 4), q + (size_t)m * DD + ch * 32 + k4);
        }
        unsigned kb = (unsigned)__cvta_generic_to_shared(qsm + 3 * QK_STQ + st * QK_STK);
#pragma unroll
        for (int r = 0; r < 4; r++) {
            int u = tid + r * 256;
            int n = u >> 3, k4 = (u & 7) * 4;
            cpa16(kb + (unsigned)((n * 36 + k4) * 4), k + (size_t)n * DD + ch * 32 + k4);
        }
    };

    issue(0, 0); cpa_commit();
    issue(1, 1); cpa_commit();

    for (int ch = 0; ch < 64; ch++) {
        if (ch + 2 < 64) cpa_wait1(); else cpa_wait0();
        __syncthreads();
        int st = ch % 3;
        unsigned (*Qs)[36] = (unsigned(*)[36])(qsm + st * QK_STQ);
        unsigned (*Ks)[36] = (unsigned(*)[36])(qsm + 3 * QK_STQ + st * QK_STK);
#pragma unroll
        for (int ks = 0; ks < 4; ks++) {
            unsigned b0[4], b1[4];
#pragma unroll
            for (int nt = 0; nt < 4; nt++) {
                b0[nt] = Ks[n_base + nt * 8 + gid][ks * 8 + tig];
                b1[nt] = Ks[n_base + nt * 8 + gid][ks * 8 + tig + 4];
            }
#pragma unroll
            for (int mt = 0; mt < 2; mt++) {
                int m = m_base + mt * 16;
                unsigned a0 = Qs[m + gid][ks * 8 + tig];
                unsigned a1 = Qs[m + 8 + gid][ks * 8 + tig];
                unsigned a2 = Qs[m + gid][ks * 8 + tig + 4];
                unsigned a3 = Qs[m + 8 + gid][ks * 8 + tig + 4];
#pragma unroll
                for (int nt = 0; nt < 4; nt++) mma_tf32(C[mt][nt], a0, a1, a2, a3, b0[nt], b1[nt]);
            }
            if (ks == 0 && ch + 2 < 64) { issue(ch + 2, (ch + 2) % 3); cpa_commit(); }
        }
    }
    __syncthreads();
    float (*Lsm)[132] = (float(*)[132])qsm;
    float rkn[8];
#pragma unroll
    for (int nt = 0; nt < 4; nt++) {
        int n = n_base + nt * 8 + 2 * tig;
        rkn[nt * 2]     = rsqrtf(fmaxf(kn[bh * 128 + n], 1e-24f));
        rkn[nt * 2 + 1] = rsqrtf(fmaxf(kn[bh * 128 + n + 1], 1e-24f));
    }
#pragma unroll
    for (int mt = 0; mt < 2; mt++)
#pragma unroll
        for (int half = 0; half < 2; half++) {
            int m = m_base + mt * 16 + gid + half * 8;
            float invq = rsqrtf(fmaxf(qn[bh * 128 + m0 + m], 1e-24f));
#pragma unroll
            for (int nt = 0; nt < 4; nt++) {
                int n = n_base + nt * 8 + 2 * tig;
                Lsm[m][n]     = C[mt][nt][half * 2 + 0] * invq * rkn[nt * 2];
                Lsm[m][n + 1] = C[mt][nt][half * 2 + 1] * invq * rkn[nt * 2 + 1];
            }
        }
    __syncthreads();
    {
        int row = wid * 8;
        for (int rr = 0; rr < 8; rr++, row++) {
            float v[4];
#pragma unroll
            for (int j = 0; j < 4; j++) v[j] = Lsm[row][lane + j * 32];
            float mx = fmaxf(fmaxf(v[0], v[1]), fmaxf(v[2], v[3]));
            for (int o = 16; o; o >>= 1) mx = fmaxf(mx, __shfl_xor_sync(0xffffffffu, mx, o));
            float sum = 0.f;
#pragma unroll
            for (int j = 0; j < 4; j++) { v[j] = __expf(v[j] - mx); sum += v[j]; }
            for (int o = 16; o; o >>= 1) sum += __shfl_xor_sync(0xffffffffu, sum, o);
            float inv = 1.f / sum;
            float* ap = A + ((size_t)(bh * 128 + m0 + row)) * 128;
#pragma unroll
            for (int j = 0; j < 4; j++) ap[lane + j * 32] = __uint_as_float(cvt1(v[j] * inv));
        }
    }
}

// ---------------- A @ V + normalized Q (raw loads, raw-sumsq norms) ----------
__global__ __launch_bounds__(256) void av_tf32(const float* __restrict__ Aa1,
                                               const float* __restrict__ V1,
                                               const float* __restrict__ Q1,
                                               const float* __restrict__ qn1,
                                               float* __restrict__ o1,
                                               const float* __restrict__ Aa2,
                                               const float* __restrict__ V2,
                                               const float* __restrict__ Q2,
                                               const float* __restrict__ qn2,
                                               float* __restrict__ o2) {
    __shared__ unsigned Ap[128][36];
    __shared__ unsigned Vs[32][136];
    const float* Aa; const float* V; const float* Q; const float* qn; float* outp;
    if (blockIdx.z == 0) { Aa = Aa1; V = V1; Q = Q1; qn = qn1; outp = o1; }
    else                 { Aa = Aa2; V = V2; Q = Q2; qn = qn2; outp = o2; }
    int bh = blockIdx.x;
    int n0 = blockIdx.y * 128;
    const float* a = Aa + (size_t)bh * 128 * 128;
    const float* v = V + (size_t)bh * 128 * DD + n0;
    int tid = threadIdx.x, lane = tid & 31, wid = tid >> 5;
    int gid = lane >> 2, tig = lane & 3;
    int m_base = (wid >> 2) * 64, n_base = (wid & 3) * 32;
    float C[4][4][4];
#pragma unroll
    for (int x = 0; x < 4; x++)
#pragma unroll
        for (int y = 0; y < 4; y++)
#pragma unroll
            for (int d = 0; d < 4; d++) C[x][y][d] = 0.f;
    uint4 pa[4], pv[4];
#pragma unroll
    for (int r = 0; r < 4; r++) {
        int e = (tid + r * 256) * 4;
        int m = e >> 5, kk = e & 31;
        pa[r] = *(const uint4*)&a[(size_t)m * 128 + kk];
    }
#pragma unroll
    for (int r = 0; r < 4; r++) {
        int e = (tid + r * 256) * 4;
        int kk = e >> 7, n = e & 127;
        pv[r] = *(const uint4*)&v[(size_t)kk * DD + n];
    }
    for (int ch = 0; ch < 4; ch++) {
#pragma unroll
        for (int r = 0; r < 4; r++) {
            int e = (tid + r * 256) * 4;
            int m = e >> 5, kk = e & 31;
            *(uint4*)&Ap[m][kk] = pa[r];
        }
#pragma unroll
        for (int r = 0; r < 4; r++) {
            int e = (tid + r * 256) * 4;
            int kk = e >> 7, n = e & 127;
            *(uint4*)&Vs[kk][n] = pv[r];
        }
        __syncthreads();
        if (ch + 1 < 4) {
            int k0 = (ch + 1) * 32;
#pragma unroll
            for (int r = 0; r < 4; r++) {
                int e = (tid + r * 256) * 4;
                int m = e >> 5, kk = e & 31;
                pa[r] = *(const uint4*)&a[(size_t)m * 128 + k0 + kk];
            }
#pragma unroll
            for (int r = 0; r < 4; r++) {
                int e = (tid + r * 256) * 4;
                int kk = e >> 7, n = e & 127;
                pv[r] = *(const uint4*)&v[(size_t)(k0 + kk) * DD + n];
            }
        }
#pragma unroll
        for (int ks = 0; ks < 4; ks++) {
            unsigned b0[4], b1[4];
#pragma unroll
            for (int nt = 0; nt < 4; nt++) {
                b0[nt] = Vs[ks * 8 + tig][n_base + nt * 8 + gid];
                b1[nt] = Vs[ks * 8 + tig + 4][n_base + nt * 8 + gid];
            }
#pragma unroll
            for (int mt = 0; mt < 4; mt++) {
                int m = m_base + mt * 16;
                unsigned a0 = Ap[m + gid][ks * 8 + tig];
                unsigned a1 = Ap[m + 8 + gid][ks * 8 + tig];
                unsigned a2 = Ap[m + gid][ks * 8 + tig + 4];
                unsigned a3 = Ap[m + 8 + gid][ks * 8 + tig + 4];
#pragma unroll
                for (int nt = 0; nt < 4; nt++) mma_tf32(C[mt][nt], a0, a1, a2, a3, b0[nt], b1[nt]);
            }
        }
        __syncthreads();
    }
#pragma unroll
    for (int mt = 0; mt < 4; mt++)
#pragma unroll
        for (int half = 0; half < 2; half++) {
            int m = m_base + mt * 16 + gid + half * 8;
            float invq = rsqrtf(fmaxf(qn[bh * 128 + m], 1e-24f));
            const float* qp = Q + ((size_t)(bh * 128 + m)) * DD + n0;
            float* op = outp + ((size_t)(bh * 128 + m)) * DD + n0;
#pragma unroll
            for (int nt = 0; nt < 4; nt++) {
                int n = n_base + nt * 8 + 2 * tig;
                float2 t;
                t.x = C[mt][nt][half * 2 + 0] + qp[n] * invq;
                t.y = C[mt][nt][half * 2 + 1] + qp[n + 1] * invq;
                *(float2*)&op[n] = t;
            }
        }
}

// ---------------- merge o3+o4 back to NCHW (pre-rounded) ---------------------
__global__ __launch_bounds__(256) void merge_kernel(const float* __restrict__ o3,
                                                    const float* __restrict__ o4,
                                                    float* __restrict__ out) {
    int r = blockIdx.x;
    int i = r & 127, bh = r >> 7;
    int b = bh >> 3, hd = bh & 7;
    __shared__ float t3[128][17];
    __shared__ float t4[128][17];
    const float* p3 = o3 + ((size_t)bh * Hh + i) * DD;
    const float* p4 = o4 + (size_t)bh * Ww * DD + i * 16;
    for (int idx = threadIdx.x; idx < 2048; idx += 256) {
        int w = idx >> 4, c = idx & 15;
        t3[w][c] = p3[idx];
        t4[w][c] = p4[(size_t)w * DD + c];
    }
    __syncthreads();
    for (int idx = threadIdx.x; idx < 2048; idx += 256) {
        int c = idx >> 7, w = idx & 127;
        out[((size_t)(b * Cc + hd * 16 + c) * Hh + i) * Ww + w] =
            __uint_as_float(cvt1(t3[w][c] + t4[w][c]));
    }
}

// ---------------- launch -----------------------------------------------------
#define SMEM_CONV (6 * 32 * 136 * 4)
#define SMEM_DW (PROWS * PS * 4)
#define SMEM_LN (128 * 128 * 4)

extern "C" void kernel_launch(void* const* d_in, const int* in_sizes, int n_in,
                              void* d_out, int out_size) {
    const float* x    = (const float*)d_in[0];
    const float* ln_w = (const float*)d_in[1];
    const float* ln_b = (const float*)d_in[2];
    const float* wd1  = (const float*)d_in[3];
    const float* gd1  = (const float*)d_in[4];
    const float* bd1  = (const float*)d_in[5];
    const float* wd2  = (const float*)d_in[6];
    const float* gd2  = (const float*)d_in[7];
    const float* bd2  = (const float*)d_in[8];
    const float* wd3  = (const float*)d_in[9];
    const float* gd3  = (const float*)d_in[10];
    const float* bd3  = (const float*)d_in[11];
    const float* w_out1 = (const float*)d_in[12];
    const float* w1 = (const float*)d_in[13]; const float* b1 = (const float*)d_in[14];
    const float* w2 = (const float*)d_in[15]; const float* b2 = (const float*)d_in[16];
    const float* w3 = (const float*)d_in[17]; const float* b3 = (const float*)d_in[18];
    const float* w4 = (const float*)d_in[19]; const float* b4 = (const float*)d_in[20];
    const float* w5 = (const float*)d_in[21]; const float* b5 = (const float*)d_in[22];
    const float* w6 = (const float*)d_in[23]; const float* b6 = (const float*)d_in[24];
    const float* w_out2 = (const float*)d_in[25];
    float* outp = (float*)d_out;

    float *p_x1, *p_y, *p_s, *p_out2, *p_hwc1, *p_whc1, *p_whc2;
    float *p_A1, *p_A2, *p_n1, *p_n2, *p_n3, *p_acc;
    float *p_wp1, *p_wp2, *p_wp3, *p_wpo1, *p_wpo2;
    cudaGetSymbolAddress((void**)&p_x1, g_x1);
    cudaGetSymbolAddress((void**)&p_y, g_y);
    cudaGetSymbolAddress((void**)&p_s, g_s);
    cudaGetSymbolAddress((void**)&p_out2, g_out2);
    cudaGetSymbolAddress((void**)&p_hwc1, g_hwc1);
    cudaGetSymbolAddress((void**)&p_whc1, g_whc1);
    cudaGetSymbolAddress((void**)&p_whc2, g_whc2);
    cudaGetSymbolAddress((void**)&p_A1, g_A1);
    cudaGetSymbolAddress((void**)&p_A2, g_A2);
    cudaGetSymbolAddress((void**)&p_n1, g_n_hwc1);
    cudaGetSymbolAddress((void**)&p_n2, g_n_whc1);
    cudaGetSymbolAddress((void**)&p_n3, g_n_whc2);
    cudaGetSymbolAddress((void**)&p_acc, g_acc);
    cudaGetSymbolAddress((void**)&p_wp1, g_wp1);
    cudaGetSymbolAddress((void**)&p_wp2, g_wp2);
    cudaGetSymbolAddress((void**)&p_wp3, g_wp3);
    cudaGetSymbolAddress((void**)&p_wpo1, g_wpo1);
    cudaGetSymbolAddress((void**)&p_wpo2, g_wpo2);

    cudaFuncSetAttribute(dw_kernel, cudaFuncAttributeMaxDynamicSharedMemorySize, SMEM_DW);
    cudaFuncSetAttribute(conv_gemm, cudaFuncAttributeMaxDynamicSharedMemorySize, SMEM_CONV);
    cudaFuncSetAttribute(qk_tf32, cudaFuncAttributeMaxDynamicSharedMemorySize, SMEM_QK);
    cudaFuncSetAttribute(ln_round, cudaFuncAttributeMaxDynamicSharedMemorySize, SMEM_LN);

    static cudaStream_t s2 = nullptr;
    static cudaEvent_t evL = nullptr, evD = nullptr;
    if (s2 == nullptr) {
        cudaStreamCreateWithFlags(&s2, cudaStreamNonBlocking);
        cudaEventCreateWithFlags(&evL, cudaEventDisableTiming);
        cudaEventCreateWithFlags(&evD, cudaEventDisableTiming);
    }

    ConvJob jy2 = { p_s, p_wp2, nullptr, p_hwc1, p_acc + 256, 9, 6, 0 };
    ConvJob jy3 = { p_s, p_wp3, nullptr, p_whc1, p_acc + 512, 9, 12, 0 };
    ConvJob jy1 = { p_s, p_wp1, nullptr, p_y, p_acc, 1, 1, 0 };
    ConvJob jo2 = { p_s, p_wpo1, x, p_out2, nullptr, 1, 1, 1 };
    ConvJob jo1 = { p_whc2, p_wpo2, nullptr, p_x1, nullptr, 1, 1, 1 };
    ConvJob jfin = { p_out2, p_wpo2, x, outp, nullptr, 1, 1, 0 };

    pack_all<<<1344, 256>>>(wd1, wd2, wd3, w_out1, w_out2);
    ln_round<<<Bb * Hh, 128, SMEM_LN>>>(x, ln_w, ln_b, p_x1, p_s);
    // fork: dw on side stream
    cudaEventRecord(evL, 0);
    cudaStreamWaitEvent(s2, evL, 0);
    dw_kernel<<<Bb * Cc, 256, SMEM_DW, s2>>>(p_x1, w1, b1, w2, b2, w3, b3, w4, b4, w5, b5, w6, b6, p_whc2);
    cudaEventRecord(evD, s2);
    // main chain
    conv_gemm<<<dim3(Bb * Hh, 3), 128, SMEM_CONV>>>(jy2, jy3, jy1);
    bnrelu3<<<NELEM / 256, 256>>>(p_y, p_hwc1, p_whc1, gd1, bd1, gd2, bd2, gd3, bd3, p_s);
    cudaStreamWaitEvent(0, evD, 0);
    conv_gemm<<<dim3(Bb * Hh, 2), 128, SMEM_CONV>>>(jo2, jo1, jo2);

    rearrange_both<<<dim3(BH * Hh, 2), 256>>>(p_x1, p_hwc1, p_whc1, p_n1, p_n2,
                                              p_out2, p_whc2, p_n3);

    qk_tf32<<<dim3(BH, 2, 2), 256, SMEM_QK>>>(p_whc2, p_hwc1, p_n3, p_n1, p_A1,
                                              p_whc1, p_whc2, p_n2, p_n3, p_A2);
    av_tf32<<<dim3(BH, 16, 2), 256>>>(p_A1, p_hwc1, p_whc2, p_n3, p_s,
                                      p_A2, p_whc2, p_whc1, p_n2, p_y);

    merge_kernel<<<BH * Hh, 256>>>(p_s, p_y, p_out2);
    conv_gemm<<<dim3(Bb * Hh, 1), 128, SMEM_CONV>>>(jfin, jfin, jfin);
}

// round 16
// speedup vs baseline: 1.0950x; 1.0950x over previous
#include <cuda_runtime.h>

#define Bb 8
#define Cc 128
#define Hh 128
#define Ww 128
#define HW 16384
#define NELEM (Bb*Cc*HW)
#define DD 2048
#define BH 64

// ---------------- scratch ----------------------------------------------------
__device__ float g_x1[NELEM];
__device__ float g_y[NELEM];
__device__ float g_s[NELEM];
__device__ float g_out2[NELEM];
__device__ float g_hwc1[NELEM];
__device__ float g_whc1[NELEM];
__device__ float g_whc2[NELEM];
__device__ float g_A1[BH*Hh*Ww];
__device__ float g_A2[BH*Hh*Ww];
__device__ float g_n_hwc1[BH*Hh];
__device__ float g_n_whc1[BH*Ww];
__device__ float g_n_whc2[BH*Ww];
__device__ float g_acc[3*256];
__device__ float g_wp1[Cc*Cc];
__device__ float g_wp2[9*Cc*Cc];
__device__ float g_wp3[9*Cc*Cc];
__device__ float g_wpo1[Cc*Cc];
__device__ float g_wpo2[Cc*Cc];

// ---------------- tf32 helpers ----------------------------------------------
__device__ __forceinline__ unsigned cvt1(float f) {
    unsigned u; asm("cvt.rna.tf32.f32 %0, %1;" : "=r"(u) : "f"(f)); return u;
}
__device__ __forceinline__ void mma_tf32(float* c, unsigned a0, unsigned a1,
                                         unsigned a2, unsigned a3,
                                         unsigned b0, unsigned b1) {
    asm volatile("mma.sync.aligned.m16n8k8.row.col.f32.tf32.tf32.f32 "
                 "{%0,%1,%2,%3}, {%4,%5,%6,%7}, {%8,%9}, {%0,%1,%2,%3};"
                 : "+f"(c[0]), "+f"(c[1]), "+f"(c[2]), "+f"(c[3])
                 : "r"(a0), "r"(a1), "r"(a2), "r"(a3), "r"(b0), "r"(b1));
}
__device__ __forceinline__ void cpa8(unsigned dst, const void* src, int sz) {
    asm volatile("cp.async.ca.shared.global [%0], [%1], 8, %2;" :: "r"(dst), "l"(src), "r"(sz));
}
__device__ __forceinline__ void cpa16(unsigned dst, const void* src) {
    asm volatile("cp.async.cg.shared.global [%0], [%1], 16;" :: "r"(dst), "l"(src));
}
__device__ __forceinline__ void cpa_commit() { asm volatile("cp.async.commit_group;"); }
__device__ __forceinline__ void cpa_wait0() { asm volatile("cp.async.wait_group 0;"); }
__device__ __forceinline__ void cpa_wait1() { asm volatile("cp.async.wait_group 1;"); }

// ---------------- single-launch weight pack + accumulator zeroing ------------
__device__ __forceinline__ void pack_one(const float* __restrict__ w,
                                         float* __restrict__ wp, int taps, int idx) {
    int co = idx / (Cc * taps);
    int rem = idx % (Cc * taps);
    int ci = rem / taps;
    int tap = rem % taps;
    wp[(tap * Cc + ci) * Cc + co] = __uint_as_float(cvt1(w[idx]));
}
__global__ void pack_all(const float* __restrict__ wd1, const float* __restrict__ wd2,
                         const float* __restrict__ wd3, const float* __restrict__ wo1,
                         const float* __restrict__ wo2) {
    int idx = blockIdx.x * 256 + threadIdx.x;
    if (idx < 768) g_acc[idx] = 0.f;
    if (idx < BH * Ww) g_n_whc1[idx] = 0.f;
    else if (idx < 2 * BH * Ww) g_n_whc2[idx - BH * Ww] = 0.f;
    if (idx < 16384)            pack_one(wd1, g_wp1, 1, idx);
    else if (idx < 163840)      pack_one(wd2, g_wp2, 9, idx - 16384);
    else if (idx < 311296)      pack_one(wd3, g_wp3, 9, idx - 163840);
    else if (idx < 327680)      pack_one(wo1, g_wpo1, 1, idx - 311296);
    else if (idx < 344064)      pack_one(wo2, g_wpo2, 1, idx - 327680);
}

// ---------------- LN + rounded-x, single global read -------------------------
__global__ __launch_bounds__(128) void ln_round(const float* __restrict__ x,
                                                const float* __restrict__ lw,
                                                const float* __restrict__ lb,
                                                float* __restrict__ o,
                                                float* __restrict__ xr) {
    extern __shared__ float row[];
    int bi = blockIdx.x;
    int b = bi >> 7, i = bi & 127;
    int w = threadIdx.x;
    size_t off = (size_t)b * Cc * HW + i * Ww + w;
    const float* p = x + off;
    float s = 0.f, sq = 0.f;
    for (int c = 0; c < Cc; c++) {
        float v = p[(size_t)c * HW];
        row[c * 128 + w] = v;
        s += v; sq += v * v;
    }
    float mu = s * (1.f / Cc);
    float var = sq * (1.f / Cc) - mu * mu;
    float r = rsqrtf(var + 1e-5f);
    float* op = o + off;
    float* xp = xr + off;
    for (int c = 0; c < Cc; c++) {
        float v = row[c * 128 + w];
        op[(size_t)c * HW] = (v - mu) * r * lw[c] + lb[c];
        xp[(size_t)c * HW] = __uint_as_float(cvt1(v));
    }
}

// ---------------- conv jobs --------------------------------------------------
struct ConvJob {
    const float* in;
    const float* wp;
    const float* resid;
    float* out;
    float* acc;
    int taps, dil, rnd;
};

// ======== 256-thread, 64x32 warp tiles (best for short-K 1x1 convs) ==========
__global__ __launch_bounds__(256, 2) void conv_gemm256(ConvJob j0, ConvJob j1, ConvJob j2) {
    extern __shared__ unsigned smem[];
    unsigned (*Asm)[136] = (unsigned(*)[136])smem;
    unsigned (*Bsm)[136] = (unsigned(*)[136])(smem + 3 * 32 * 136);
    ConvJob j = (blockIdx.y == 0) ? j0 : (blockIdx.y == 1 ? j1 : j2);
    const int taps = j.taps, dil = j.dil;
    int bi = blockIdx.x;
    int b = bi >> 7, i = bi & 127;
    int tid = threadIdx.x, lane = tid & 31, wid = tid >> 5;
    int gid = lane >> 2, tig = lane & 3;
    int m_base = (wid >> 2) * 64, n_base = (wid & 3) * 32;
    float C[4][4][4];
#pragma unroll
    for (int a = 0; a < 4; a++)
#pragma unroll
        for (int c = 0; c < 4; c++)
#pragma unroll
            for (int d = 0; d < 4; d++) C[a][c][d] = 0.f;
    const int nch = taps * 4;
    const float* inb = j.in + (size_t)b * Cc * HW;
    const int w2 = (tid & 63) * 2;
    const int kb2 = tid >> 6;
    const int w4 = (tid & 31) * 4;
    const int kb4 = tid >> 5;

    auto issueA = [&](int ch, int st) {
        const float* wpB = j.wp + (size_t)ch * 32 * 128;
        unsigned base = (unsigned)__cvta_generic_to_shared(&Asm[st * 32][0]);
#pragma unroll
        for (int r = 0; r < 4; r++) {
            int u = tid + r * 256;
            int kka = u >> 5, m4 = (u & 31) * 4;
            cpa16(base + (unsigned)((kka * 136 + m4) * 4), wpB + kka * 128 + m4);
        }
    };
    auto issueB = [&](int ch, int st) {
        unsigned dst0 = (unsigned)__cvta_generic_to_shared(&Bsm[st * 32][0]);
        if (taps == 9) {
            int tap = ch >> 2, ciBase = (ch & 3) * 32;
            int dy = (tap / 3 - 1) * dil, dx = (tap % 3 - 1) * dil;
            int ii = i + dy;
            int wd = w2 + dx;
            int ok = ((unsigned)ii < 128u && (unsigned)wd < 127u) ? 8 : 0;
            const float* src = inb + (size_t)(ciBase + kb2) * HW + ii * 128 + wd;
            unsigned dst = dst0 + (unsigned)((kb2 * 136 + w2) * 4);
#pragma unroll
            for (int r = 0; r < 8; r++)
                cpa8(dst + (unsigned)(r * 4 * 136 * 4), src + (size_t)r * 4 * HW, ok);
        } else {
            int ciBase = ch * 32;
            const float* src = inb + (size_t)(ciBase + kb4) * HW + i * 128 + w4;
            unsigned dst = dst0 + (unsigned)((kb4 * 136 + w4) * 4);
#pragma unroll
            for (int r = 0; r < 4; r++)
                cpa16(dst + (unsigned)(r * 8 * 136 * 4), src + (size_t)r * 8 * HW);
        }
    };

    issueA(0, 0); issueB(0, 0); cpa_commit();
    issueA(1, 1); issueB(1, 1); cpa_commit();

    for (int ch = 0; ch < nch; ch++) {
        if (ch + 2 < nch) cpa_wait1(); else cpa_wait0();
        __syncthreads();
        int st = ch % 3;
        unsigned (*As)[136] = &Asm[st * 32];
        unsigned (*Bs)[136] = &Bsm[st * 32];
#pragma unroll
        for (int ks = 0; ks < 4; ks++) {
            unsigned b0[4], b1[4];
#pragma unroll
            for (int nt = 0; nt < 4; nt++) {
                b0[nt] = Bs[ks * 8 + tig][n_base + nt * 8 + gid];
                b1[nt] = Bs[ks * 8 + tig + 4][n_base + nt * 8 + gid];
            }
#pragma unroll
            for (int mt = 0; mt < 4; mt++) {
                int m = m_base + mt * 16;
                unsigned a0 = As[ks * 8 + tig][m + gid];
                unsigned a1 = As[ks * 8 + tig][m + 8 + gid];
                unsigned a2 = As[ks * 8 + tig + 4][m + gid];
                unsigned a3 = As[ks * 8 + tig + 4][m + 8 + gid];
#pragma unroll
                for (int nt = 0; nt < 4; nt++) mma_tf32(C[mt][nt], a0, a1, a2, a3, b0[nt], b1[nt]);
            }
            if (ks == 0 && ch + 2 < nch) {
                int st2 = (ch + 2) % 3;
                issueA(ch + 2, st2); issueB(ch + 2, st2); cpa_commit();
            }
        }
    }
    float* sacc = (float*)smem;
    if (j.acc) {
        __syncthreads();
        if (tid < 256) sacc[tid] = 0.f;
        __syncthreads();
    }
#pragma unroll
    for (int mt = 0; mt < 4; mt++)
#pragma unroll
        for (int half = 0; half < 2; half++) {
            int m = m_base + mt * 16 + gid + half * 8;
            size_t base = ((size_t)(b * 128 + m) * 128 + i) * 128;
            float rs = 0.f, rq = 0.f;
#pragma unroll
            for (int nt = 0; nt < 4; nt++) {
                int n = n_base + nt * 8 + 2 * tig;
                float v0 = C[mt][nt][half * 2 + 0];
                float v1 = C[mt][nt][half * 2 + 1];
                if (j.resid) { v0 += j.resid[base + n]; v1 += j.resid[base + n + 1]; }
                if (j.rnd) { v0 = __uint_as_float(cvt1(v0)); v1 = __uint_as_float(cvt1(v1)); }
                rs += v0 + v1;
                rq += v0 * v0 + v1 * v1;
                float2 t = {v0, v1};
                *(float2*)&j.out[base + n] = t;
            }
            if (j.acc) {
                rs += __shfl_xor_sync(0xffffffffu, rs, 1);
                rs += __shfl_xor_sync(0xffffffffu, rs, 2);
                rq += __shfl_xor_sync(0xffffffffu, rq, 1);
                rq += __shfl_xor_sync(0xffffffffu, rq, 2);
                if (tig == 0) { atomicAdd(&sacc[m], rs); atomicAdd(&sacc[128 + m], rq); }
            }
        }
    if (j.acc) {
        __syncthreads();
        if (tid < 128) {
            atomicAdd(&j.acc[tid], sacc[tid]);
            atomicAdd(&j.acc[128 + tid], sacc[128 + tid]);
        }
    }
}

// ======== 128-thread, 64x64 warp tiles (best for long-K dilated convs) =======
__global__ __launch_bounds__(128, 2) void conv_gemm128(ConvJob j0, ConvJob j1, ConvJob j2) {
    extern __shared__ unsigned smem[];
    unsigned (*Asm)[136] = (unsigned(*)[136])smem;
    unsigned (*Bsm)[136] = (unsigned(*)[136])(smem + 3 * 32 * 136);
    ConvJob j = (blockIdx.y == 0) ? j0 : (blockIdx.y == 1 ? j1 : j2);
    const int taps = j.taps, dil = j.dil;
    int bi = blockIdx.x;
    int b = bi >> 7, i = bi & 127;
    int tid = threadIdx.x, lane = tid & 31, wid = tid >> 5;
    int gid = lane >> 2, tig = lane & 3;
    int m_base = (wid >> 1) * 64, n_base = (wid & 1) * 64;
    float C[4][8][4];
#pragma unroll
    for (int a = 0; a < 4; a++)
#pragma unroll
        for (int c = 0; c < 8; c++)
#pragma unroll
            for (int d = 0; d < 4; d++) C[a][c][d] = 0.f;
    const int nch = taps * 4;
    const float* inb = j.in + (size_t)b * Cc * HW;
    const int w2 = (tid & 63) * 2;
    const int kb2 = tid >> 6;
    const int w4 = (tid & 31) * 4;
    const int kb4 = tid >> 5;

    auto issueA = [&](int ch, int st) {
        const float* wpB = j.wp + (size_t)ch * 32 * 128;
        unsigned base = (unsigned)__cvta_generic_to_shared(&Asm[st * 32][0]);
#pragma unroll
        for (int r = 0; r < 8; r++) {
            int u = tid + r * 128;
            int kka = u >> 5, m4 = (u & 31) * 4;
            cpa16(base + (unsigned)((kka * 136 + m4) * 4), wpB + kka * 128 + m4);
        }
    };
    auto issueB = [&](int ch, int st) {
        unsigned dst0 = (unsigned)__cvta_generic_to_shared(&Bsm[st * 32][0]);
        if (taps == 9) {
            int tap = ch >> 2, ciBase = (ch & 3) * 32;
            int dy = (tap / 3 - 1) * dil, dx = (tap % 3 - 1) * dil;
            int ii = i + dy;
            int wd = w2 + dx;
            int ok = ((unsigned)ii < 128u && (unsigned)wd < 127u) ? 8 : 0;
            const float* src = inb + (size_t)(ciBase + kb2) * HW + ii * 128 + wd;
            unsigned dst = dst0 + (unsigned)((kb2 * 136 + w2) * 4);
#pragma unroll
            for (int r = 0; r < 16; r++)
                cpa8(dst + (unsigned)(r * 2 * 136 * 4), src + (size_t)r * 2 * HW, ok);
        } else {
            int ciBase = ch * 32;
            const float* src = inb + (size_t)(ciBase + kb4) * HW + i * 128 + w4;
            unsigned dst = dst0 + (unsigned)((kb4 * 136 + w4) * 4);
#pragma unroll
            for (int r = 0; r < 8; r++)
                cpa16(dst + (unsigned)(r * 4 * 136 * 4), src + (size_t)r * 4 * HW);
        }
    };

    issueA(0, 0); issueB(0, 0); cpa_commit();
    issueA(1, 1); issueB(1, 1); cpa_commit();

    for (int ch = 0; ch < nch; ch++) {
        if (ch + 2 < nch) cpa_wait1(); else cpa_wait0();
        __syncthreads();
        int st = ch % 3;
        unsigned (*As)[136] = &Asm[st * 32];
        unsigned (*Bs)[136] = &Bsm[st * 32];
#pragma unroll
        for (int ks = 0; ks < 4; ks++) {
            unsigned b0[8], b1[8];
#pragma unroll
            for (int nt = 0; nt < 8; nt++) {
                b0[nt] = Bs[ks * 8 + tig][n_base + nt * 8 + gid];
                b1[nt] = Bs[ks * 8 + tig + 4][n_base + nt * 8 + gid];
            }
#pragma unroll
            for (int mt = 0; mt < 4; mt++) {
                int m = m_base + mt * 16;
                unsigned a0 = As[ks * 8 + tig][m + gid];
                unsigned a1 = As[ks * 8 + tig][m + 8 + gid];
                unsigned a2 = As[ks * 8 + tig + 4][m + gid];
                unsigned a3 = As[ks * 8 + tig + 4][m + 8 + gid];
#pragma unroll
                for (int nt = 0; nt < 8; nt++) mma_tf32(C[mt][nt], a0, a1, a2, a3, b0[nt], b1[nt]);
            }
            if (ks == 0 && ch + 2 < nch) {
                int st2 = (ch + 2) % 3;
                issueA(ch + 2, st2); issueB(ch + 2, st2); cpa_commit();
            }
        }
    }
    float* sacc = (float*)smem;
    if (j.acc) {
        __syncthreads();
        sacc[tid] = 0.f; sacc[128 + tid] = 0.f;
        __syncthreads();
    }
#pragma unroll
    for (int mt = 0; mt < 4; mt++)
#pragma unroll
        for (int half = 0; half < 2; half++) {
            int m = m_base + mt * 16 + gid + half * 8;
            size_t base = ((size_t)(b * 128 + m) * 128 + i) * 128;
            float rs = 0.f, rq = 0.f;
#pragma unroll
            for (int nt = 0; nt < 8; nt++) {
                int n = n_base + nt * 8 + 2 * tig;
                float v0 = C[mt][nt][half * 2 + 0];
                float v1 = C[mt][nt][half * 2 + 1];
                if (j.resid) { v0 += j.resid[base + n]; v1 += j.resid[base + n + 1]; }
                if (j.rnd) { v0 = __uint_as_float(cvt1(v0)); v1 = __uint_as_float(cvt1(v1)); }
                rs += v0 + v1;
                rq += v0 * v0 + v1 * v1;
                float2 t = {v0, v1};
                *(float2*)&j.out[base + n] = t;
            }
            if (j.acc) {
                rs += __shfl_xor_sync(0xffffffffu, rs, 1);
                rs += __shfl_xor_sync(0xffffffffu, rs, 2);
                rq += __shfl_xor_sync(0xffffffffu, rq, 1);
                rq += __shfl_xor_sync(0xffffffffu, rq, 2);
                if (tig == 0) { atomicAdd(&sacc[m], rs); atomicAdd(&sacc[128 + m], rq); }
            }
        }
    if (j.acc) {
        __syncthreads();
        atomicAdd(&j.acc[tid], sacc[tid]);
        atomicAdd(&j.acc[128 + tid], sacc[128 + tid]);
    }
}

// ---------------- BN-ReLU-sum, float4, inline stats finalize -----------------
__global__ __launch_bounds__(256) void bnrelu3(const float* __restrict__ y1,
                                               const float* __restrict__ y2,
                                               const float* __restrict__ y3,
                                               const float* __restrict__ g1, const float* __restrict__ b1,
                                               const float* __restrict__ g2, const float* __restrict__ b2,
                                               const float* __restrict__ g3, const float* __restrict__ b3,
                                               float* __restrict__ s) {
    int idx4 = blockIdx.x * 256 + threadIdx.x;   // float4 index
    int c = (idx4 >> 12) & 127;                   // 4096 float4 per channel-plane
    const float inv = 1.f / (float)(Bb * HW);
    float m1 = g_acc[c] * inv;
    float r1 = rsqrtf(g_acc[128 + c] * inv - m1 * m1 + 1e-5f);
    float m2 = g_acc[256 + c] * inv;
    float r2 = rsqrtf(g_acc[384 + c] * inv - m2 * m2 + 1e-5f);
    float m3 = g_acc[512 + c] * inv;
    float r3 = rsqrtf(g_acc[640 + c] * inv - m3 * m3 + 1e-5f);
    float s1 = r1 * g1[c], o1 = b1[c] - m1 * s1;
    float s2 = r2 * g2[c], o2 = b2[c] - m2 * s2;
    float s3 = r3 * g3[c], o3 = b3[c] - m3 * s3;
    float4 a = *(const float4*)&y1[idx4 * 4];
    float4 bq = *(const float4*)&y2[idx4 * 4];
    float4 cc = *(const float4*)&y3[idx4 * 4];
    float4 o;
    o.x = __uint_as_float(cvt1(fmaxf(a.x * s1 + o1, 0.f) + fmaxf(bq.x * s2 + o2, 0.f) + fmaxf(cc.x * s3 + o3, 0.f)));
    o.y = __uint_as_float(cvt1(fmaxf(a.y * s1 + o1, 0.f) + fmaxf(bq.y * s2 + o2, 0.f) + fmaxf(cc.y * s3 + o3, 0.f)));
    o.z = __uint_as_float(cvt1(fmaxf(a.z * s1 + o1, 0.f) + fmaxf(bq.z * s2 + o2, 0.f) + fmaxf(cc.z * s3 + o3, 0.f)));
    o.w = __uint_as_float(cvt1(fmaxf(a.w * s1 + o1, 0.f) + fmaxf(bq.w * s2 + o2, 0.f) + fmaxf(cc.w * s3 + o3, 0.f)));
    *(float4*)&s[idx4 * 4] = o;
}

// ---------------- six depthwise convs, padded plane --------------------------
#define PS 136
#define PROWS 134
__global__ __launch_bounds__(256) void dw_kernel(const float* __restrict__ x1,
    const float* __restrict__ w1, const float* __restrict__ b1,
    const float* __restrict__ w2, const float* __restrict__ b2,
    const float* __restrict__ w3, const float* __restrict__ b3,
    const float* __restrict__ w4, const float* __restrict__ b4,
    const float* __restrict__ w5, const float* __restrict__ b5,
    const float* __restrict__ w6, const float* __restrict__ b6,
    float* __restrict__ out) {
    extern __shared__ float plane[];
    int bc = blockIdx.x;
    int c = bc & 127;
    const float* p = x1 + (size_t)bc * HW;
    for (int idx = threadIdx.x; idx < PROWS * PS; idx += 256) plane[idx] = 0.f;
    __syncthreads();
    for (int idx = threadIdx.x; idx < HW; idx += 256) {
        int i = idx >> 7, w = idx & 127;
        plane[(i + 3) * PS + (w + 3)] = p[idx];
    }
    float f1[5], f2[5], f4[9], f5[7], f6[7];
#pragma unroll
    for (int j = 0; j < 5; j++) { f1[j] = w1[c * 5 + j]; f2[j] = w2[c * 5 + j]; }
#pragma unroll
    for (int j = 0; j < 9; j++) f4[j] = w4[c * 9 + j];
#pragma unroll
    for (int j = 0; j < 7; j++) { f5[j] = w5[c * 7 + j]; f6[j] = w6[c * 7 + j]; }
    float f3 = w3[c];
    float bias = b1[c] + b2[c] + b3[c] + b4[c] + b5[c] + b6[c];
    __syncthreads();
    for (int idx = threadIdx.x; idx < HW; idx += 256) {
        int i = idx >> 7, w = idx & 127;
        const float* cp = &plane[(i + 3) * PS + (w + 3)];
        float acc = bias + f3 * cp[0];
#pragma unroll
        for (int j = 0; j < 5; j++) acc += f1[j] * cp[j - 2];
#pragma unroll
        for (int j = 0; j < 5; j++) acc += f2[j] * cp[(j - 2) * PS];
#pragma unroll
        for (int pq = 0; pq < 9; pq++) acc += f4[pq] * cp[(pq / 3 - 1) * PS + (pq % 3 - 1)];
#pragma unroll
        for (int j = 0; j < 7; j++) acc += f5[j] * cp[j - 3];
#pragma unroll
        for (int j = 0; j < 7; j++) acc += f6[j] * cp[(j - 3) * PS];
        out[(size_t)bc * HW + idx] = __uint_as_float(cvt1(acc));
    }
}

// ---------------- rearranges + fused row-norm partials -----------------------
__global__ __launch_bounds__(256) void rearrange_both(const float* __restrict__ out1,
                                                      float* __restrict__ hwc,
                                                      float* __restrict__ whc,
                                                      float* __restrict__ nrm,
                                                      float* __restrict__ nacc1,
                                                      const float* __restrict__ out2,
                                                      float* __restrict__ whc2,
                                                      float* __restrict__ nacc2) {
    int r = blockIdx.x;
    int i = r & 127, bh = r >> 7;
    int b = bh >> 3, hd = bh & 7;
    __shared__ float tile[16][129];
    __shared__ float sw[128];
    if (blockIdx.y == 0) {
        __shared__ float red[256];
        float sq = 0.f;
        for (int idx = threadIdx.x; idx < 2048; idx += 256) {
            int c = idx >> 7, w = idx & 127;
            float v = out1[((size_t)(b * Cc + hd * 16 + c) * Hh + i) * Ww + w];
            tile[c][w] = v;
            sq += v * v;
        }
        red[threadIdx.x] = sq;
        __syncthreads();
        for (int o = 128; o; o >>= 1) { if (threadIdx.x < o) red[threadIdx.x] += red[threadIdx.x + o]; __syncthreads(); }
        if (threadIdx.x == 0) nrm[bh * 128 + i] = red[0];
        float* dh = hwc + ((size_t)bh * Hh + i) * DD;
        float* dw = whc + (size_t)bh * Ww * DD + i * 16;
        for (int idx = threadIdx.x; idx < 2048; idx += 256) {
            int w = idx >> 4, c = idx & 15;
            float v = tile[c][w];
            dh[idx] = v;
            dw[(size_t)w * DD + c] = v;
            float s = v * v;
            s += __shfl_xor_sync(0xffffffffu, s, 1);
            s += __shfl_xor_sync(0xffffffffu, s, 2);
            s += __shfl_xor_sync(0xffffffffu, s, 4);
            s += __shfl_xor_sync(0xffffffffu, s, 8);
            if ((threadIdx.x & 15) == 0) sw[w] = s;
        }
        __syncthreads();
        if (threadIdx.x < 128) atomicAdd(&nacc1[bh * 128 + threadIdx.x], sw[threadIdx.x]);
    } else {
        for (int idx = threadIdx.x; idx < 2048; idx += 256) {
            int c = idx >> 7, w = idx & 127;
            tile[c][w] = out2[((size_t)(b * Cc + hd * 16 + c) * Hh + i) * Ww + w];
        }
        __syncthreads();
        float* d = whc2 + (size_t)bh * Ww * DD + i * 16;
        for (int idx = threadIdx.x; idx < 2048; idx += 256) {
            int w = idx >> 4, c = idx & 15;
            float v = tile[c][w];
            d[(size_t)w * DD + c] = v;
            float s = v * v;
            s += __shfl_xor_sync(0xffffffffu, s, 1);
            s += __shfl_xor_sync(0xffffffffu, s, 2);
            s += __shfl_xor_sync(0xffffffffu, s, 4);
            s += __shfl_xor_sync(0xffffffffu, s, 8);
            if ((threadIdx.x & 15) == 0) sw[w] = s;
        }
        __syncthreads();
        if (threadIdx.x < 128) atomicAdd(&nacc2[bh * 128 + threadIdx.x], sw[threadIdx.x]);
    }
}

// ---------------- QK^T + softmax: 3-stage cp.async, raw-sumsq norms ----------
#define QK_STQ (64 * 36)
#define QK_STK (128 * 36)
#define SMEM_QK (3 * (QK_STQ + QK_STK) * 4)

__global__ __launch_bounds__(256) void qk_tf32(const float* __restrict__ Q1,
                                               const float* __restrict__ K1,
                                               const float* __restrict__ qn1,
                                               const float* __restrict__ kn1,
                                               float* __restrict__ A1,
                                               const float* __restrict__ Q2,
                                               const float* __restrict__ K2,
                                               const float* __restrict__ qn2,
                                               const float* __restrict__ kn2,
                                               float* __restrict__ A2) {
    extern __shared__ unsigned qsm[];
    const float* Q; const float* K; const float* qn; const float* kn; float* A;
    if (blockIdx.z == 0) { Q = Q1; K = K1; qn = qn1; kn = kn1; A = A1; }
    else                 { Q = Q2; K = K2; qn = qn2; kn = kn2; A = A2; }
    int bh = blockIdx.x;
    int m0 = blockIdx.y * 64;
    const float* q = Q + (size_t)(bh * 128 + m0) * DD;
    const float* k = K + (size_t)bh * 128 * DD;
    int tid = threadIdx.x, lane = tid & 31, wid = tid >> 5;
    int gid = lane >> 2, tig = lane & 3;
    int m_base = (wid >> 2) * 32, n_base = (wid & 3) * 32;
    float C[2][4][4];
#pragma unroll
    for (int a = 0; a < 2; a++)
#pragma unroll
        for (int c = 0; c < 4; c++)
#pragma unroll
            for (int d = 0; d < 4; d++) C[a][c][d] = 0.f;

    auto issue = [&](int ch, int st) {
        unsigned qb = (unsigned)__cvta_generic_to_shared(qsm + st * QK_STQ);
#pragma unroll
        for (int r = 0; r < 2; r++) {
            int u = tid + r * 256;
            int m = u >> 3, k4 = (u & 7) * 4;
            cpa16(qb + (unsigned)((m * 36 + k4) * 4), q + (size_t)m * DD + ch * 32 + k4);
        }
        unsigned kb = (unsigned)__cvta_generic_to_shared(qsm + 3 * QK_STQ + st * QK_STK);
#pragma unroll
        for (int r = 0; r < 4; r++) {
            int u = tid + r * 256;
            int n = u >> 3, k4 = (u & 7) * 4;
            cpa16(kb + (unsigned)((n * 36 + k4) * 4), k + (size_t)n * DD + ch * 32 + k4);
        }
    };

    issue(0, 0); cpa_commit();
    issue(1, 1); cpa_commit();

    for (int ch = 0; ch < 64; ch++) {
        if (ch + 2 < 64) cpa_wait1(); else cpa_wait0();
        __syncthreads();
        int st = ch % 3;
        unsigned (*Qs)[36] = (unsigned(*)[36])(qsm + st * QK_STQ);
        unsigned (*Ks)[36] = (unsigned(*)[36])(qsm + 3 * QK_STQ + st * QK_STK);
#pragma unroll
        for (int ks = 0; ks < 4; ks++) {
            unsigned b0[4], b1[4];
#pragma unroll
            for (int nt = 0; nt < 4; nt++) {
                b0[nt] = Ks[n_base + nt * 8 + gid][ks * 8 + tig];
                b1[nt] = Ks[n_base + nt * 8 + gid][ks * 8 + tig + 4];
            }
#pragma unroll
            for (int mt = 0; mt < 2; mt++) {
                int m = m_base + mt * 16;
                unsigned a0 = Qs[m + gid][ks * 8 + tig];
                unsigned a1 = Qs[m + 8 + gid][ks * 8 + tig];
                unsigned a2 = Qs[m + gid][ks * 8 + tig + 4];
                unsigned a3 = Qs[m + 8 + gid][ks * 8 + tig + 4];
#pragma unroll
                for (int nt = 0; nt < 4; nt++) mma_tf32(C[mt][nt], a0, a1, a2, a3, b0[nt], b1[nt]);
            }
            if (ks == 0 && ch + 2 < 64) { issue(ch + 2, (ch + 2) % 3); cpa_commit(); }
        }
    }
    __syncthreads();
    float (*Lsm)[132] = (float(*)[132])qsm;
    float rkn[8];
#pragma unroll
    for (int nt = 0; nt < 4; nt++) {
        int n = n_base + nt * 8 + 2 * tig;
        rkn[nt * 2]     = rsqrtf(fmaxf(kn[bh * 128 + n], 1e-24f));
        rkn[nt * 2 + 1] = rsqrtf(fmaxf(kn[bh * 128 + n + 1], 1e-24f));
    }
#pragma unroll
    for (int mt = 0; mt < 2; mt++)
#pragma unroll
        for (int half = 0; half < 2; half++) {
            int m = m_base + mt * 16 + gid + half * 8;
            float invq = rsqrtf(fmaxf(qn[bh * 128 + m0 + m], 1e-24f));
#pragma unroll
            for (int nt = 0; nt < 4; nt++) {
                int n = n_base + nt * 8 + 2 * tig;
                Lsm[m][n]     = C[mt][nt][half * 2 + 0] * invq * rkn[nt * 2];
                Lsm[m][n + 1] = C[mt][nt][half * 2 + 1] * invq * rkn[nt * 2 + 1];
            }
        }
    __syncthreads();
    {
        int row = wid * 8;
        for (int rr = 0; rr < 8; rr++, row++) {
            float v[4];
#pragma unroll
            for (int j = 0; j < 4; j++) v[j] = Lsm[row][lane + j * 32];
            float mx = fmaxf(fmaxf(v[0], v[1]), fmaxf(v[2], v[3]));
            for (int o = 16; o; o >>= 1) mx = fmaxf(mx, __shfl_xor_sync(0xffffffffu, mx, o));
            float sum = 0.f;
#pragma unroll
            for (int j = 0; j < 4; j++) { v[j] = __expf(v[j] - mx); sum += v[j]; }
            for (int o = 16; o; o >>= 1) sum += __shfl_xor_sync(0xffffffffu, sum, o);
            float inv = 1.f / sum;
            float* ap = A + ((size_t)(bh * 128 + m0 + row)) * 128;
#pragma unroll
            for (int j = 0; j < 4; j++) ap[lane + j * 32] = __uint_as_float(cvt1(v[j] * inv));
        }
    }
}

// ---------------- A @ V + normalized Q (raw loads, raw-sumsq norms) ----------
__global__ __launch_bounds__(256) void av_tf32(const float* __restrict__ Aa1,
                                               const float* __restrict__ V1,
                                               const float* __restrict__ Q1,
                                               const float* __restrict__ qn1,
                                               float* __restrict__ o1,
                                               const float* __restrict__ Aa2,
                                               const float* __restrict__ V2,
                                               const float* __restrict__ Q2,
                                               const float* __restrict__ qn2,
                                               float* __restrict__ o2) {
    __shared__ unsigned Ap[128][36];
    __shared__ unsigned Vs[32][136];
    const float* Aa; const float* V; const float* Q; const float* qn; float* outp;
    if (blockIdx.z == 0) { Aa = Aa1; V = V1; Q = Q1; qn = qn1; outp = o1; }
    else                 { Aa = Aa2; V = V2; Q = Q2; qn = qn2; outp = o2; }
    int bh = blockIdx.x;
    int n0 = blockIdx.y * 128;
    const float* a = Aa + (size_t)bh * 128 * 128;
    const float* v = V + (size_t)bh * 128 * DD + n0;
    int tid = threadIdx.x, lane = tid & 31, wid = tid >> 5;
    int gid = lane >> 2, tig = lane & 3;
    int m_base = (wid >> 2) * 64, n_base = (wid & 3) * 32;
    float C[4][4][4];
#pragma unroll
    for (int x = 0; x < 4; x++)
#pragma unroll
        for (int y = 0; y < 4; y++)
#pragma unroll
            for (int d = 0; d < 4; d++) C[x][y][d] = 0.f;
    uint4 pa[4], pv[4];
#pragma unroll
    for (int r = 0; r < 4; r++) {
        int e = (tid + r * 256) * 4;
        int m = e >> 5, kk = e & 31;
        pa[r] = *(const uint4*)&a[(size_t)m * 128 + kk];
    }
#pragma unroll
    for (int r = 0; r < 4; r++) {
        int e = (tid + r * 256) * 4;
        int kk = e >> 7, n = e & 127;
        pv[r] = *(const uint4*)&v[(size_t)kk * DD + n];
    }
    for (int ch = 0; ch < 4; ch++) {
#pragma unroll
        for (int r = 0; r < 4; r++) {
            int e = (tid + r * 256) * 4;
            int m = e >> 5, kk = e & 31;
            *(uint4*)&Ap[m][kk] = pa[r];
        }
#pragma unroll
        for (int r = 0; r < 4; r++) {
            int e = (tid + r * 256) * 4;
            int kk = e >> 7, n = e & 127;
            *(uint4*)&Vs[kk][n] = pv[r];
        }
        __syncthreads();
        if (ch + 1 < 4) {
            int k0 = (ch + 1) * 32;
#pragma unroll
            for (int r = 0; r < 4; r++) {
                int e = (tid + r * 256) * 4;
                int m = e >> 5, kk = e & 31;
                pa[r] = *(const uint4*)&a[(size_t)m * 128 + k0 + kk];
            }
#pragma unroll
            for (int r = 0; r < 4; r++) {
                int e = (tid + r * 256) * 4;
                int kk = e >> 7, n = e & 127;
                pv[r] = *(const uint4*)&v[(size_t)(k0 + kk) * DD + n];
            }
        }
#pragma unroll
        for (int ks = 0; ks < 4; ks++) {
            unsigned b0[4], b1[4];
#pragma unroll
            for (int nt = 0; nt < 4; nt++) {
                b0[nt] = Vs[ks * 8 + tig][n_base + nt * 8 + gid];
                b1[nt] = Vs[ks * 8 + tig + 4][n_base + nt * 8 + gid];
            }
#pragma unroll
            for (int mt = 0; mt < 4; mt++) {
                int m = m_base + mt * 16;
                unsigned a0 = Ap[m + gid][ks * 8 + tig];
                unsigned a1 = Ap[m + 8 + gid][ks * 8 + tig];
                unsigned a2 = Ap[m + gid][ks * 8 + tig + 4];
                unsigned a3 = Ap[m + 8 + gid][ks * 8 + tig + 4];
#pragma unroll
                for (int nt = 0; nt < 4; nt++) mma_tf32(C[mt][nt], a0, a1, a2, a3, b0[nt], b1[nt]);
            }
        }
        __syncthreads();
    }
#pragma unroll
    for (int mt = 0; mt < 4; mt++)
#pragma unroll
        for (int half = 0; half < 2; half++) {
            int m = m_base + mt * 16 + gid + half * 8;
            float invq = rsqrtf(fmaxf(qn[bh * 128 + m], 1e-24f));
            const float* qp = Q + ((size_t)(bh * 128 + m)) * DD + n0;
            float* op = outp + ((size_t)(bh * 128 + m)) * DD + n0;
#pragma unroll
            for (int nt = 0; nt < 4; nt++) {
                int n = n_base + nt * 8 + 2 * tig;
                float2 t;
                t.x = C[mt][nt][half * 2 + 0] + qp[n] * invq;
                t.y = C[mt][nt][half * 2 + 1] + qp[n + 1] * invq;
                *(float2*)&op[n] = t;
            }
        }
}

// ---------------- merge o3+o4 back to NCHW (pre-rounded) ---------------------
__global__ __launch_bounds__(256) void merge_kernel(const float* __restrict__ o3,
                                                    const float* __restrict__ o4,
                                                    float* __restrict__ out) {
    int r = blockIdx.x;
    int i = r & 127, bh = r >> 7;
    int b = bh >> 3, hd = bh & 7;
    __shared__ float t3[128][17];
    __shared__ float t4[128][17];
    const float* p3 = o3 + ((size_t)bh * Hh + i) * DD;
    const float* p4 = o4 + (size_t)bh * Ww * DD + i * 16;
    for (int idx = threadIdx.x; idx < 2048; idx += 256) {
        int w = idx >> 4, c = idx & 15;
        t3[w][c] = p3[idx];
        t4[w][c] = p4[(size_t)w * DD + c];
    }
    __syncthreads();
    for (int idx = threadIdx.x; idx < 2048; idx += 256) {
        int c = idx >> 7, w = idx & 127;
        out[((size_t)(b * Cc + hd * 16 + c) * Hh + i) * Ww + w] =
            __uint_as_float(cvt1(t3[w][c] + t4[w][c]));
    }
}

// ---------------- launch -----------------------------------------------------
#define SMEM_CONV (6 * 32 * 136 * 4)
#define SMEM_DW (PROWS * PS * 4)
#define SMEM_LN (128 * 128 * 4)

extern "C" void kernel_launch(void* const* d_in, const int* in_sizes, int n_in,
                              void* d_out, int out_size) {
    const float* x    = (const float*)d_in[0];
    const float* ln_w = (const float*)d_in[1];
    const float* ln_b = (const float*)d_in[2];
    const float* wd1  = (const float*)d_in[3];
    const float* gd1  = (const float*)d_in[4];
    const float* bd1  = (const float*)d_in[5];
    const float* wd2  = (const float*)d_in[6];
    const float* gd2  = (const float*)d_in[7];
    const float* bd2  = (const float*)d_in[8];
    const float* wd3  = (const float*)d_in[9];
    const float* gd3  = (const float*)d_in[10];
    const float* bd3  = (const float*)d_in[11];
    const float* w_out1 = (const float*)d_in[12];
    const float* w1 = (const float*)d_in[13]; const float* b1 = (const float*)d_in[14];
    const float* w2 = (const float*)d_in[15]; const float* b2 = (const float*)d_in[16];
    const float* w3 = (const float*)d_in[17]; const float* b3 = (const float*)d_in[18];
    const float* w4 = (const float*)d_in[19]; const float* b4 = (const float*)d_in[20];
    const float* w5 = (const float*)d_in[21]; const float* b5 = (const float*)d_in[22];
    const float* w6 = (const float*)d_in[23]; const float* b6 = (const float*)d_in[24];
    const float* w_out2 = (const float*)d_in[25];
    float* outp = (float*)d_out;

    float *p_x1, *p_y, *p_s, *p_out2, *p_hwc1, *p_whc1, *p_whc2;
    float *p_A1, *p_A2, *p_n1, *p_n2, *p_n3, *p_acc;
    float *p_wp1, *p_wp2, *p_wp3, *p_wpo1, *p_wpo2;
    cudaGetSymbolAddress((void**)&p_x1, g_x1);
    cudaGetSymbolAddress((void**)&p_y, g_y);
    cudaGetSymbolAddress((void**)&p_s, g_s);
    cudaGetSymbolAddress((void**)&p_out2, g_out2);
    cudaGetSymbolAddress((void**)&p_hwc1, g_hwc1);
    cudaGetSymbolAddress((void**)&p_whc1, g_whc1);
    cudaGetSymbolAddress((void**)&p_whc2, g_whc2);
    cudaGetSymbolAddress((void**)&p_A1, g_A1);
    cudaGetSymbolAddress((void**)&p_A2, g_A2);
    cudaGetSymbolAddress((void**)&p_n1, g_n_hwc1);
    cudaGetSymbolAddress((void**)&p_n2, g_n_whc1);
    cudaGetSymbolAddress((void**)&p_n3, g_n_whc2);
    cudaGetSymbolAddress((void**)&p_acc, g_acc);
    cudaGetSymbolAddress((void**)&p_wp1, g_wp1);
    cudaGetSymbolAddress((void**)&p_wp2, g_wp2);
    cudaGetSymbolAddress((void**)&p_wp3, g_wp3);
    cudaGetSymbolAddress((void**)&p_wpo1, g_wpo1);
    cudaGetSymbolAddress((void**)&p_wpo2, g_wpo2);

    cudaFuncSetAttribute(dw_kernel, cudaFuncAttributeMaxDynamicSharedMemorySize, SMEM_DW);
    cudaFuncSetAttribute(conv_gemm256, cudaFuncAttributeMaxDynamicSharedMemorySize, SMEM_CONV);
    cudaFuncSetAttribute(conv_gemm128, cudaFuncAttributeMaxDynamicSharedMemorySize, SMEM_CONV);
    cudaFuncSetAttribute(qk_tf32, cudaFuncAttributeMaxDynamicSharedMemorySize, SMEM_QK);
    cudaFuncSetAttribute(ln_round, cudaFuncAttributeMaxDynamicSharedMemorySize, SMEM_LN);

    static cudaStream_t s2 = nullptr;
    static cudaEvent_t evL = nullptr, evD = nullptr;
    if (s2 == nullptr) {
        cudaStreamCreateWithFlags(&s2, cudaStreamNonBlocking);
        cudaEventCreateWithFlags(&evL, cudaEventDisableTiming);
        cudaEventCreateWithFlags(&evD, cudaEventDisableTiming);
    }

    ConvJob jy2 = { p_s, p_wp2, nullptr, p_hwc1, p_acc + 256, 9, 6, 0 };
    ConvJob jy3 = { p_s, p_wp3, nullptr, p_whc1, p_acc + 512, 9, 12, 0 };
    ConvJob jy1 = { p_s, p_wp1, nullptr, p_y, p_acc, 1, 1, 0 };
    ConvJob jo2 = { p_s, p_wpo1, x, p_out2, nullptr, 1, 1, 1 };
    ConvJob jo1 = { p_whc2, p_wpo2, nullptr, p_x1, nullptr, 1, 1, 1 };
    ConvJob jfin = { p_out2, p_wpo2, x, outp, nullptr, 1, 1, 0 };

    pack_all<<<1344, 256>>>(wd1, wd2, wd3, w_out1, w_out2);
    ln_round<<<Bb * Hh, 128, SMEM_LN>>>(x, ln_w, ln_b, p_x1, p_s);
    // fork: dw on side stream
    cudaEventRecord(evL, 0);
    cudaStreamWaitEvent(s2, evL, 0);
    dw_kernel<<<Bb * Cc, 256, SMEM_DW, s2>>>(p_x1, w1, b1, w2, b2, w3, b3, w4, b4, w5, b5, w6, b6, p_whc2);
    cudaEventRecord(evD, s2);
    // main chain: long-K dilated convs use the 64x64 retiled kernel
    conv_gemm128<<<dim3(Bb * Hh, 3), 128, SMEM_CONV>>>(jy2, jy3, jy1);
    bnrelu3<<<NELEM / 1024, 256>>>(p_y, p_hwc1, p_whc1, gd1, bd1, gd2, bd2, gd3, bd3, p_s);
    cudaStreamWaitEvent(0, evD, 0);
    // short-K 1x1 convs use the 256-thread kernel (better latency hiding)
    conv_gemm256<<<dim3(Bb * Hh, 2), 256, SMEM_CONV>>>(jo2, jo1, jo2);

    rearrange_both<<<dim3(BH * Hh, 2), 256>>>(p_x1, p_hwc1, p_whc1, p_n1, p_n2,
                                              p_out2, p_whc2, p_n3);

    qk_tf32<<<dim3(BH, 2, 2), 256, SMEM_QK>>>(p_whc2, p_hwc1, p_n3, p_n1, p_A1,
                                              p_whc1, p_whc2, p_n2, p_n3, p_A2);
    av_tf32<<<dim3(BH, 16, 2), 256>>>(p_A1, p_hwc1, p_whc2, p_n3, p_s,
                                      p_A2, p_whc2, p_whc1, p_n2, p_y);

    merge_kernel<<<BH * Hh, 256>>>(p_s, p_y, p_out2);
    conv_gemm256<<<dim3(Bb * Hh, 1), 256, SMEM_CONV>>>(jfin, jfin, jfin);
}